// round 12
// baseline (speedup 1.0000x reference)
#include <cuda_runtime.h>
#include <math.h>

#define B_   2
#define C1_  256
#define C2_  256
#define H_   64
#define W_   64
#define HW_  4096
#define OMC  27   // offset(18) + mask(9) channels

#define NSPLIT 4            // split-K factor (dcn)
#define PART_SZ (B_ * C2_ * HW_)
#define OM_SZ   (B_ * OMC * HW_)

#define NROWS   (C1_ * 9)        // 2304 (c,k) rows
#define NROWS_P (NROWS + 4)      // + prefetch-overrun pad rows (zeros)

// Scratch (device globals — no allocation allowed)
__device__ float g_om[NSPLIT][OM_SZ];                 // offset/mask conv partials
// weights duplicated for f32x2: row rr=(c*9+k), float4[rr][col]:
//   col =      o0 (0..63): (w[o0],   w[o0],   w[o0+64], w[o0+64])
//   col = 64 + o0        : (w[o0+128],w[o0+128],w[o0+192],w[o0+192])
__device__ __align__(16) float g_wtd[NROWS_P * 128 * 4];   // 4.7 MB
__device__ float g_part[NSPLIT * PART_SZ];            // split-K partials (32 MB)
__device__ int   g_cnt[B_ * H_ * (W_ / 32)];          // per-strip counters (zero-init)

#define N_TRANS_BLK 2304   // transpose blocks (589824 elems / 256)
#define N_CONV_BLK  1024   // conv blocks (256 strips x 4 channel slices)

// f32x2 packed FMA: acc(2xf32) += a(2xf32) * b(2xf32)   [FFMA2 in SASS]
#define FFMA2(acc, a, b) \
    asm("fma.rn.f32x2 %0, %1, %2, %0;" : "+l"(acc) : "l"(a), "l"(b))

// ---------------------------------------------------------------------------
// Kernel 1 (merged): blocks [0,2304): permute+duplicate w_dcn -> g_wtd
//                    blocks [2304,3328): 3x3 conv offset_feat -> g_om partials
// ---------------------------------------------------------------------------
__global__ __launch_bounds__(256) void prep_kernel(
    const float* __restrict__ in, const float* __restrict__ w,
    const float* __restrict__ bias, const float* __restrict__ w_dcn)
{
    __shared__ float sh[16][3][36];    // input tile: 16 ch x 3 rows x 34(+2) cols
    __shared__ float wsh[16][27][9];   // weight tile: 16 ch x 27 oc x 9 taps

    const int tid = threadIdx.x;

    if (blockIdx.x < N_TRANS_BLK) {
        int i = blockIdx.x * 256 + tid;   // i < 589824 always
        int k = i % 9;
        int c = (i / 9) % C1_;
        int o = i / (9 * C1_);
        int rr = c * 9 + k;
        int oo = o & 63;
        int j  = o >> 6;
        int col  = ((j >= 2) ? 64 : 0) + oo;
        int base = (rr * 128 + col) * 4 + (j & 1) * 2;
        float v = w_dcn[i];
        g_wtd[base]     = v;
        g_wtd[base + 1] = v;
        if (blockIdx.x == 0) {   // zero the 4 pad rows (2048 floats)
            for (int z = tid; z < 4 * 128 * 4; z += 256)
                g_wtd[NROWS * 128 * 4 + z] = 0.f;
        }
        return;
    }

    const int bx    = blockIdx.x - N_TRANS_BLK;
    const int strip = bx >> 2;
    const int slice = bx & 3;
    const int b     = strip >> 7;
    const int h     = (strip & 127) >> 1;
    const int w0    = (strip & 1) * 32;
    const int oc    = tid & 31;
    const int pg    = tid >> 5;

    float acc[4] = {0.f, 0.f, 0.f, 0.f};

    for (int c0 = slice * 64; c0 < slice * 64 + 64; c0 += 16) {
        __syncthreads();
        // input tile 16x3x34 (zero-padded)
        for (int t = tid; t < 16 * 3 * 34; t += 256) {
            int c   = t / 102;
            int rem = t - c * 102;
            int r   = rem / 34;
            int col = rem - r * 34;
            int gh = h + r - 1;
            int gw = w0 + col - 1;
            float v = 0.f;
            if (gh >= 0 && gh < H_ && gw >= 0 && gw < W_)
                v = in[((b * C2_ + c0 + c) * H_ + gh) * W_ + gw];
            sh[c][r][col] = v;
        }
        // weight tile 16x27x9
        for (int t = tid; t < 16 * 27 * 9; t += 256) {
            int c   = t / 243;
            int rem = t - c * 243;
            int o   = rem / 9;
            int k   = rem - o * 9;
            wsh[c][o][k] = w[((size_t)o * C2_ + c0 + c) * 9 + k];
        }
        __syncthreads();

        if (oc < OMC) {
            #pragma unroll 4
            for (int c = 0; c < 16; ++c) {
                #pragma unroll
                for (int ky = 0; ky < 3; ++ky) {
                    float r6[6];
                    #pragma unroll
                    for (int j = 0; j < 6; ++j) r6[j] = sh[c][ky][pg * 4 + j];
                    #pragma unroll
                    for (int kx = 0; kx < 3; ++kx) {
                        float wv = wsh[c][oc][ky * 3 + kx];
                        #pragma unroll
                        for (int p = 0; p < 4; ++p)
                            acc[p] += wv * r6[p + kx];
                    }
                }
            }
        }
    }

    if (oc < OMC) {
        float bo = (slice == 0) ? bias[oc] : 0.f;
        float* op = g_om[slice] + ((size_t)b * OMC + oc) * HW_ + h * W_ + w0 + pg * 4;
        #pragma unroll
        for (int p = 0; p < 4; ++p) op[p] = acc[p] + bo;
    }
}

// ---------------------------------------------------------------------------
// Kernel 2: deformable sampling + split-K GEMM + last-block reduction.
// Grid 1024: strip (b,h,32px) x 64-channel slice.
// GEMM thread map: o0 = tid>>2 (8 distinct per warp), pg = tid&3
//   -> weight LDG.128 = 1 L1 wavefront/warp (128B, pg-twins broadcast)
//   -> LDS.128 = 64B unique/warp, conflict-free.
// Depth-3 weight register ring, zero-mov f32x2 body.
// ---------------------------------------------------------------------------
__global__ __launch_bounds__(256) void dcn_kernel(
    const float* __restrict__ x, const float* __restrict__ bias,
    float* __restrict__ out)
{
    __shared__ __align__(16) float val_sh[288][32];    // [c*9+k][px]  36 KB
    __shared__ int4   s_idx[288];                      // 4.5 KB
    __shared__ float4 s_w[288];                        // 4.5 KB
    __shared__ int    s_last;

    const int bx    = blockIdx.x;
    const int strip = bx >> 2;
    const int half  = bx & 3;
    const int cbase = half * 64;
    const int b     = strip >> 7;
    const int h     = (strip & 127) >> 1;
    const int w0    = (strip & 1) * 32;
    const int tid   = threadIdx.x;

    // ---- Phase 1: sampling metadata (per pixel x 9 taps) ----
    for (int e = tid; e < 288; e += 256) {
        int p  = e & 31;
        int k  = e >> 5;
        int ky = k / 3;
        int kx = k - ky * 3;
        int wo = w0 + p;
        const size_t base = (size_t)b * OMC * HW_ + h * W_ + wo;
        float dy = 0.f, dx = 0.f, mv = 0.f;
        #pragma unroll
        for (int s = 0; s < NSPLIT; ++s) {
            const float* omb = g_om[s] + base;
            dy += omb[(2 * k) * HW_];
            dx += omb[(2 * k + 1) * HW_];
            mv += omb[(18 + k) * HW_];
        }
        float m  = 1.f / (1.f + expf(-mv));

        float ys = (float)(h - 1 + ky) + dy;
        float xs = (float)(wo - 1 + kx) + dx;
        float y0f = floorf(ys), x0f = floorf(xs);
        float ly = ys - y0f, lx = xs - x0f;
        int y0 = (int)y0f, x0 = (int)x0f;
        int y1 = y0 + 1,   x1 = x0 + 1;

        bool vy0 = (y0 >= 0) && (y0 < H_);
        bool vy1 = (y1 >= 0) && (y1 < H_);
        bool vx0 = (x0 >= 0) && (x0 < W_);
        bool vx1 = (x1 >= 0) && (x1 < W_);
        int cy0 = min(max(y0, 0), H_ - 1), cy1 = min(max(y1, 0), H_ - 1);
        int cx0 = min(max(x0, 0), W_ - 1), cx1 = min(max(x1, 0), W_ - 1);

        float w00 = (vy0 && vx0) ? (1.f - ly) * (1.f - lx) * m : 0.f;
        float w01 = (vy0 && vx1) ? (1.f - ly) * lx * m : 0.f;
        float w10 = (vy1 && vx0) ? ly * (1.f - lx) * m : 0.f;
        float w11 = (vy1 && vx1) ? ly * lx * m : 0.f;

        s_idx[e] = make_int4(cy0 * W_ + cx0, cy0 * W_ + cx1,
                             cy1 * W_ + cx0, cy1 * W_ + cx1);
        s_w[e]   = make_float4(w00, w01, w10, w11);
    }
    __syncthreads();

    const int o0 = tid >> 2;   // out-channel base (8 distinct per warp)
    const int pg = tid & 3;    // pixel-pair group (pixels pg*8..pg*8+7)
    const int gp = tid & 31;   // gather: pixel
    const int gc = tid >> 5;   // gather: channel sub-index (stride 8)

    unsigned long long acc2[4][4];
    #pragma unroll
    for (int j = 0; j < 4; ++j)
        #pragma unroll
        for (int pp = 0; pp < 4; ++pp) acc2[j][pp] = 0ULL;

    for (int c0 = cbase; c0 < cbase + 64; c0 += 32) {
        // ---- gather 32 channels x 9 taps x 32 pixels ----
        for (int cc = gc; cc < 32; cc += 8) {
            const float* xp = x + ((size_t)b * C1_ + c0 + cc) * HW_;
            #pragma unroll
            for (int k = 0; k < 9; ++k) {
                int e = k * 32 + gp;
                int4   id = s_idx[e];
                float4 wv = s_w[e];
                float v = wv.x * __ldg(xp + id.x) + wv.y * __ldg(xp + id.y)
                        + wv.z * __ldg(xp + id.z) + wv.w * __ldg(xp + id.w);
                val_sh[cc * 9 + k][gp] = v;
            }
        }
        __syncthreads();

        // ---- GEMM: 288 steps, zero-mov f32x2, depth-3 LDG.128 ring ----
        const ulonglong2* wq = reinterpret_cast<const ulonglong2*>(g_wtd)
                             + (size_t)(c0 * 9) * 128;
        ulonglong2 rA[3], rB[3];
        #pragma unroll
        for (int d = 0; d < 3; ++d) {
            rA[d] = __ldg(wq + (size_t)d * 128 + o0);
            rB[d] = __ldg(wq + (size_t)d * 128 + 64 + o0);
        }

        for (int m = 0; m < 288; m += 3) {
            #pragma unroll
            for (int j = 0; j < 3; ++j) {
                const int ck = m + j;
                ulonglong2 wA = rA[j];
                ulonglong2 wB = rB[j];
                rA[j] = __ldg(wq + (size_t)(ck + 3) * 128 + o0);
                rB[j] = __ldg(wq + (size_t)(ck + 3) * 128 + 64 + o0);

                const ulonglong2* vp =
                    reinterpret_cast<const ulonglong2*>(&val_sh[ck][pg * 8]);
                ulonglong2 v01 = vp[0];
                ulonglong2 v23 = vp[1];

                FFMA2(acc2[0][0], wA.x, v01.x);
                FFMA2(acc2[0][1], wA.x, v01.y);
                FFMA2(acc2[0][2], wA.x, v23.x);
                FFMA2(acc2[0][3], wA.x, v23.y);
                FFMA2(acc2[1][0], wA.y, v01.x);
                FFMA2(acc2[1][1], wA.y, v01.y);
                FFMA2(acc2[1][2], wA.y, v23.x);
                FFMA2(acc2[1][3], wA.y, v23.y);
                FFMA2(acc2[2][0], wB.x, v01.x);
                FFMA2(acc2[2][1], wB.x, v01.y);
                FFMA2(acc2[2][2], wB.x, v23.x);
                FFMA2(acc2[2][3], wB.x, v23.y);
                FFMA2(acc2[3][0], wB.y, v01.x);
                FFMA2(acc2[3][1], wB.y, v01.y);
                FFMA2(acc2[3][2], wB.y, v23.x);
                FFMA2(acc2[3][3], wB.y, v23.y);
            }
        }
        __syncthreads();
    }

    // ---- write partials ----
    #pragma unroll
    for (int j = 0; j < 4; ++j) {
        int o = o0 + ((j >= 2) ? 64 : 0) + ((j & 1) ? 64 : 0) * 2;
        // j: 0 -> o0, 1 -> o0+64, 2 -> o0+128, 3 -> o0+192
        o = o0 + j * 64;
        float* op = g_part + (size_t)half * PART_SZ
                  + ((size_t)(b * C2_ + o)) * HW_ + h * W_ + w0 + pg * 8;
        #pragma unroll
        for (int pp = 0; pp < 4; ++pp) {
            float lo, hi;
            asm("mov.b64 {%0, %1}, %2;" : "=f"(lo), "=f"(hi) : "l"(acc2[j][pp]));
            op[pp * 2]     = lo;
            op[pp * 2 + 1] = hi;
        }
    }

    // ---- last-block reduction for this strip ----
    __threadfence();
    __syncthreads();
    if (tid == 0) {
        int old = atomicAdd(&g_cnt[strip], 1);
        s_last = (old == NSPLIT - 1);
        if (old == NSPLIT - 1) g_cnt[strip] = 0;   // reset for next graph replay
    }
    __syncthreads();

    if (s_last) {
        __threadfence();                 // acquire: see other blocks' partials
        const int oc = tid;              // 256 threads = 256 out channels
        const float bo = bias[oc];
        const size_t off = ((size_t)(b * C2_ + oc)) * HW_ + h * W_ + w0;
        #pragma unroll
        for (int px = 0; px < 32; px += 4) {
            float4 s = make_float4(bo, bo, bo, bo);
            #pragma unroll
            for (int sl = 0; sl < NSPLIT; ++sl) {
                float4 v = *reinterpret_cast<const float4*>(
                    g_part + (size_t)sl * PART_SZ + off + px);
                s.x += v.x; s.y += v.y; s.z += v.z; s.w += v.w;
            }
            *reinterpret_cast<float4*>(out + off + px) = s;
        }
    }
}

// ---------------------------------------------------------------------------
extern "C" void kernel_launch(void* const* d_in, const int* in_sizes, int n_in,
                              void* d_out, int out_size) {
    const float* x      = (const float*)d_in[0];
    const float* offs   = (const float*)d_in[1];
    const float* w_om   = (const float*)d_in[2];
    const float* b_om   = (const float*)d_in[3];
    const float* w_dcn  = (const float*)d_in[4];
    const float* b_dcn  = (const float*)d_in[5];
    float* out = (float*)d_out;

    prep_kernel<<<N_TRANS_BLK + N_CONV_BLK, 256>>>(offs, w_om, b_om, w_dcn);
    dcn_kernel<<<B_ * H_ * (W_ / 32) * NSPLIT, 256>>>(x, b_dcn, out);
}

// round 13
// speedup vs baseline: 1.1531x; 1.1531x over previous
#include <cuda_runtime.h>
#include <math.h>

#define B_   2
#define C1_  256
#define C2_  256
#define H_   64
#define W_   64
#define HW_  4096
#define OMC  27   // offset(18) + mask(9) channels

#define NSPLIT 4            // split-K factor (dcn)
#define PART_SZ (B_ * C2_ * HW_)
#define OM_SZ   (B_ * OMC * HW_)

#define NROWS   (C1_ * 9)        // 2304 (c,k) rows
#define NROWS_P (NROWS + 4)      // + prefetch-overrun pad rows

// Scratch (device globals — no allocation allowed)
__device__ float g_om[NSPLIT][OM_SZ];                 // offset/mask conv partials
// weights duplicated for f32x2: row rr=(c*9+k), float4[rr][col]:
//   col =      o0 (0..63): (w[o0],   w[o0],   w[o0+64], w[o0+64])
//   col = 64 + o0        : (w[o0+128],w[o0+128],w[o0+192],w[o0+192])
__device__ __align__(16) float g_wtd[NROWS_P * 128 * 4];   // 4.7 MB
__device__ float g_part[NSPLIT * PART_SZ];            // split-K partials (32 MB)
__device__ int   g_cnt[B_ * H_ * (W_ / 32)];          // per-strip counters (zero-init)

#define N_TRANS_BLK 2304   // transpose blocks (589824 elems / 256)
#define N_CONV_BLK  1024   // conv blocks (256 strips x 4 channel slices)

// f32x2 packed FMA: acc(2xf32) += a(2xf32) * b(2xf32)   [FFMA2 in SASS]
#define FFMA2(acc, a, b) \
    asm("fma.rn.f32x2 %0, %1, %2, %0;" : "+l"(acc) : "l"(a), "l"(b))

// ---------------------------------------------------------------------------
// Kernel 1 (merged): blocks [0,2304): permute+duplicate w_dcn -> g_wtd
//                    blocks [2304,3328): 3x3 conv offset_feat -> g_om partials
// ---------------------------------------------------------------------------
__global__ __launch_bounds__(256) void prep_kernel(
    const float* __restrict__ in, const float* __restrict__ w,
    const float* __restrict__ bias, const float* __restrict__ w_dcn)
{
    __shared__ float sh[16][3][36];    // input tile: 16 ch x 3 rows x 34(+2) cols
    __shared__ float wsh[16][27][9];   // weight tile: 16 ch x 27 oc x 9 taps

    const int tid = threadIdx.x;

    if (blockIdx.x < N_TRANS_BLK) {
        int i = blockIdx.x * 256 + tid;   // i < 589824 always
        int k = i % 9;
        int c = (i / 9) % C1_;
        int o = i / (9 * C1_);
        int rr = c * 9 + k;
        int oo = o & 63;
        int j  = o >> 6;
        int col  = ((j >= 2) ? 64 : 0) + oo;
        int base = (rr * 128 + col) * 4 + (j & 1) * 2;
        float v = w_dcn[i];
        g_wtd[base]     = v;
        g_wtd[base + 1] = v;
        if (blockIdx.x == 0) {   // zero the 4 pad rows (2048 floats)
            for (int z = tid; z < 4 * 128 * 4; z += 256)
                g_wtd[NROWS * 128 * 4 + z] = 0.f;
        }
        return;
    }

    const int bx    = blockIdx.x - N_TRANS_BLK;
    const int strip = bx >> 2;
    const int slice = bx & 3;
    const int b     = strip >> 7;
    const int h     = (strip & 127) >> 1;
    const int w0    = (strip & 1) * 32;
    const int oc    = tid & 31;
    const int pg    = tid >> 5;

    float acc[4] = {0.f, 0.f, 0.f, 0.f};

    for (int c0 = slice * 64; c0 < slice * 64 + 64; c0 += 16) {
        __syncthreads();
        // input tile 16x3x34 (zero-padded)
        for (int t = tid; t < 16 * 3 * 34; t += 256) {
            int c   = t / 102;
            int rem = t - c * 102;
            int r   = rem / 34;
            int col = rem - r * 34;
            int gh = h + r - 1;
            int gw = w0 + col - 1;
            float v = 0.f;
            if (gh >= 0 && gh < H_ && gw >= 0 && gw < W_)
                v = in[((b * C2_ + c0 + c) * H_ + gh) * W_ + gw];
            sh[c][r][col] = v;
        }
        // weight tile 16x27x9
        for (int t = tid; t < 16 * 27 * 9; t += 256) {
            int c   = t / 243;
            int rem = t - c * 243;
            int o   = rem / 9;
            int k   = rem - o * 9;
            wsh[c][o][k] = w[((size_t)o * C2_ + c0 + c) * 9 + k];
        }
        __syncthreads();

        if (oc < OMC) {
            #pragma unroll 4
            for (int c = 0; c < 16; ++c) {
                #pragma unroll
                for (int ky = 0; ky < 3; ++ky) {
                    float r6[6];
                    #pragma unroll
                    for (int j = 0; j < 6; ++j) r6[j] = sh[c][ky][pg * 4 + j];
                    #pragma unroll
                    for (int kx = 0; kx < 3; ++kx) {
                        float wv = wsh[c][oc][ky * 3 + kx];
                        #pragma unroll
                        for (int p = 0; p < 4; ++p)
                            acc[p] += wv * r6[p + kx];
                    }
                }
            }
        }
    }

    if (oc < OMC) {
        float bo = (slice == 0) ? bias[oc] : 0.f;
        float* op = g_om[slice] + ((size_t)b * OMC + oc) * HW_ + h * W_ + w0 + pg * 4;
        #pragma unroll
        for (int p = 0; p < 4; ++p) op[p] = acc[p] + bo;
    }
}

// ---------------------------------------------------------------------------
// Kernel 2: deformable sampling + split-K GEMM + last-block reduction.
// Grid 1024: strip (b,h,32px) x 64-channel slice.
// GEMM map: o0 = tid&63, pg = tid>>6 (R8 mapping — proven fastest).
// Depth-4 ring of 2x LDG.128 (8 reqs in flight), zero-mov f32x2 body.
// ---------------------------------------------------------------------------
__global__ __launch_bounds__(256, 3) void dcn_kernel(
    const float* __restrict__ x, const float* __restrict__ bias,
    float* __restrict__ out)
{
    __shared__ __align__(16) float val_sh[288][32];    // [c*9+k][px]  36 KB
    __shared__ int4   s_idx[288];                      // 4.5 KB
    __shared__ float4 s_w[288];                        // 4.5 KB
    __shared__ int    s_last;

    const int bx    = blockIdx.x;
    const int strip = bx >> 2;
    const int half  = bx & 3;
    const int cbase = half * 64;
    const int b     = strip >> 7;
    const int h     = (strip & 127) >> 1;
    const int w0    = (strip & 1) * 32;
    const int tid   = threadIdx.x;

    // ---- Phase 1: sampling metadata (per pixel x 9 taps) ----
    for (int e = tid; e < 288; e += 256) {
        int p  = e & 31;
        int k  = e >> 5;
        int ky = k / 3;
        int kx = k - ky * 3;
        int wo = w0 + p;
        const size_t base = (size_t)b * OMC * HW_ + h * W_ + wo;
        float dy = 0.f, dx = 0.f, mv = 0.f;
        #pragma unroll
        for (int s = 0; s < NSPLIT; ++s) {
            const float* omb = g_om[s] + base;
            dy += omb[(2 * k) * HW_];
            dx += omb[(2 * k + 1) * HW_];
            mv += omb[(18 + k) * HW_];
        }
        float m  = 1.f / (1.f + expf(-mv));

        float ys = (float)(h - 1 + ky) + dy;
        float xs = (float)(wo - 1 + kx) + dx;
        float y0f = floorf(ys), x0f = floorf(xs);
        float ly = ys - y0f, lx = xs - x0f;
        int y0 = (int)y0f, x0 = (int)x0f;
        int y1 = y0 + 1,   x1 = x0 + 1;

        bool vy0 = (y0 >= 0) && (y0 < H_);
        bool vy1 = (y1 >= 0) && (y1 < H_);
        bool vx0 = (x0 >= 0) && (x0 < W_);
        bool vx1 = (x1 >= 0) && (x1 < W_);
        int cy0 = min(max(y0, 0), H_ - 1), cy1 = min(max(y1, 0), H_ - 1);
        int cx0 = min(max(x0, 0), W_ - 1), cx1 = min(max(x1, 0), W_ - 1);

        float w00 = (vy0 && vx0) ? (1.f - ly) * (1.f - lx) * m : 0.f;
        float w01 = (vy0 && vx1) ? (1.f - ly) * lx * m : 0.f;
        float w10 = (vy1 && vx0) ? ly * (1.f - lx) * m : 0.f;
        float w11 = (vy1 && vx1) ? ly * lx * m : 0.f;

        s_idx[e] = make_int4(cy0 * W_ + cx0, cy0 * W_ + cx1,
                             cy1 * W_ + cx0, cy1 * W_ + cx1);
        s_w[e]   = make_float4(w00, w01, w10, w11);
    }
    __syncthreads();

    const int o0 = tid & 63;   // out-channel base (o0, +64, +128, +192)
    const int pg = tid >> 6;   // pixel-pair group (pixels pg*8..pg*8+7)
    const int gp = tid & 31;   // gather: pixel
    const int gc = tid >> 5;   // gather: channel sub-index (stride 8)

    unsigned long long acc2[4][4];
    #pragma unroll
    for (int j = 0; j < 4; ++j)
        #pragma unroll
        for (int pp = 0; pp < 4; ++pp) acc2[j][pp] = 0ULL;

    for (int c0 = cbase; c0 < cbase + 64; c0 += 32) {
        // ---- gather 32 channels x 9 taps x 32 pixels ----
        for (int cc = gc; cc < 32; cc += 8) {
            const float* xp = x + ((size_t)b * C1_ + c0 + cc) * HW_;
            #pragma unroll
            for (int k = 0; k < 9; ++k) {
                int e = k * 32 + gp;
                int4   id = s_idx[e];
                float4 wv = s_w[e];
                float v = wv.x * __ldg(xp + id.x) + wv.y * __ldg(xp + id.y)
                        + wv.z * __ldg(xp + id.z) + wv.w * __ldg(xp + id.w);
                val_sh[cc * 9 + k][gp] = v;
            }
        }
        __syncthreads();

        // ---- GEMM: 288 steps, zero-mov f32x2, depth-4 dual-LDG.128 ring ----
        const ulonglong2* wq = reinterpret_cast<const ulonglong2*>(g_wtd)
                             + (size_t)(c0 * 9) * 128;
        ulonglong2 rA[4], rB[4];
        #pragma unroll
        for (int d = 0; d < 4; ++d) {
            rA[d] = __ldg(wq + (size_t)d * 128 + o0);
            rB[d] = __ldg(wq + (size_t)d * 128 + 64 + o0);
        }

        for (int m = 0; m < 288; m += 4) {
            #pragma unroll
            for (int j = 0; j < 4; ++j) {
                const int ck = m + j;
                ulonglong2 wA = rA[j];
                ulonglong2 wB = rB[j];
                // prefetch row ck+4 (pad rows keep this in-bounds at the tail)
                rA[j] = __ldg(wq + (size_t)(ck + 4) * 128 + o0);
                rB[j] = __ldg(wq + (size_t)(ck + 4) * 128 + 64 + o0);

                const ulonglong2* vp =
                    reinterpret_cast<const ulonglong2*>(&val_sh[ck][pg * 8]);
                ulonglong2 v01 = vp[0];
                ulonglong2 v23 = vp[1];

                FFMA2(acc2[0][0], wA.x, v01.x);
                FFMA2(acc2[0][1], wA.x, v01.y);
                FFMA2(acc2[0][2], wA.x, v23.x);
                FFMA2(acc2[0][3], wA.x, v23.y);
                FFMA2(acc2[1][0], wA.y, v01.x);
                FFMA2(acc2[1][1], wA.y, v01.y);
                FFMA2(acc2[1][2], wA.y, v23.x);
                FFMA2(acc2[1][3], wA.y, v23.y);
                FFMA2(acc2[2][0], wB.x, v01.x);
                FFMA2(acc2[2][1], wB.x, v01.y);
                FFMA2(acc2[2][2], wB.x, v23.x);
                FFMA2(acc2[2][3], wB.x, v23.y);
                FFMA2(acc2[3][0], wB.y, v01.x);
                FFMA2(acc2[3][1], wB.y, v01.y);
                FFMA2(acc2[3][2], wB.y, v23.x);
                FFMA2(acc2[3][3], wB.y, v23.y);
            }
        }
        __syncthreads();
    }

    // ---- write partials ----
    #pragma unroll
    for (int j = 0; j < 4; ++j) {
        int o = o0 + j * 64;
        float* op = g_part + (size_t)half * PART_SZ
                  + ((size_t)(b * C2_ + o)) * HW_ + h * W_ + w0 + pg * 8;
        #pragma unroll
        for (int pp = 0; pp < 4; ++pp) {
            float lo, hi;
            asm("mov.b64 {%0, %1}, %2;" : "=f"(lo), "=f"(hi) : "l"(acc2[j][pp]));
            op[pp * 2]     = lo;
            op[pp * 2 + 1] = hi;
        }
    }

    // ---- last-block reduction for this strip ----
    __threadfence();
    __syncthreads();
    if (tid == 0) {
        int old = atomicAdd(&g_cnt[strip], 1);
        s_last = (old == NSPLIT - 1);
        if (old == NSPLIT - 1) g_cnt[strip] = 0;   // reset for next graph replay
    }
    __syncthreads();

    if (s_last) {
        __threadfence();                 // acquire: see other blocks' partials
        const int oc = tid;              // 256 threads = 256 out channels
        const float bo = bias[oc];
        const size_t off = ((size_t)(b * C2_ + oc)) * HW_ + h * W_ + w0;
        #pragma unroll
        for (int px = 0; px < 32; px += 4) {
            float4 s = make_float4(bo, bo, bo, bo);
            #pragma unroll
            for (int sl = 0; sl < NSPLIT; ++sl) {
                float4 v = *reinterpret_cast<const float4*>(
                    g_part + (size_t)sl * PART_SZ + off + px);
                s.x += v.x; s.y += v.y; s.z += v.z; s.w += v.w;
            }
            *reinterpret_cast<float4*>(out + off + px) = s;
        }
    }
}

// ---------------------------------------------------------------------------
extern "C" void kernel_launch(void* const* d_in, const int* in_sizes, int n_in,
                              void* d_out, int out_size) {
    const float* x      = (const float*)d_in[0];
    const float* offs   = (const float*)d_in[1];
    const float* w_om   = (const float*)d_in[2];
    const float* b_om   = (const float*)d_in[3];
    const float* w_dcn  = (const float*)d_in[4];
    const float* b_dcn  = (const float*)d_in[5];
    float* out = (float*)d_out;

    prep_kernel<<<N_TRANS_BLK + N_CONV_BLK, 256>>>(offs, w_om, b_om, w_dcn);
    dcn_kernel<<<B_ * H_ * (W_ / 32) * NSPLIT, 256>>>(x, b_dcn, out);
}

// round 14
// speedup vs baseline: 1.3710x; 1.1890x over previous
#include <cuda_runtime.h>
#include <math.h>

#define B_   2
#define C1_  256
#define C2_  256
#define H_   64
#define W_   64
#define HW_  4096
#define OMC  27   // offset(18) + mask(9) channels

#define NSPLIT 4            // split-K factor (dcn)
#define PART_SZ (B_ * C2_ * HW_)
#define OM_SZ   (B_ * OMC * HW_)

#define NROWS   (C1_ * 9)        // 2304 (c,k) rows
#define NROWS_P (NROWS + 4)      // + prefetch-overrun pad rows (zeros)

// Scratch (device globals — no allocation allowed)
__device__ float g_om[NSPLIT][OM_SZ];              // offset/mask conv partials
__device__ float g_wt[NROWS_P * C2_];              // w_dcn transposed: [c][k][o]
__device__ float g_part[NSPLIT * PART_SZ];         // split-K partials (32 MB)
__device__ int   g_cnt[B_ * H_ * (W_ / 32)];       // per-strip counters (zero-init)

#define N_TRANS_BLK 2304   // transpose blocks (589824 elems / 256)
#define N_CONV_BLK  1024   // conv blocks (256 strips x 4 channel slices)

// f32x2 packed-FMA helpers (sm_100+ PTX; FFMA2 in SASS)
#define BCAST2(dst, s) asm("mov.b64 %0, {%1, %1};" : "=l"(dst) : "f"(s))
#define FFMA2(acc, a, b) \
    asm("fma.rn.f32x2 %0, %1, %2, %0;" : "+l"(acc) : "l"(a), "l"(b))

// ---------------------------------------------------------------------------
// Kernel 1 (merged): blocks [0,2304): transpose w_dcn [o][c][k] -> [c][k][o]
//                    blocks [2304,3328): 3x3 conv offset_feat -> g_om partials
// ---------------------------------------------------------------------------
__global__ __launch_bounds__(256) void prep_kernel(
    const float* __restrict__ in, const float* __restrict__ w,
    const float* __restrict__ bias, const float* __restrict__ w_dcn)
{
    __shared__ float sh[16][3][36];    // input tile: 16 ch x 3 rows x 34(+2) cols
    __shared__ float wsh[16][27][9];   // weight tile: 16 ch x 27 oc x 9 taps

    const int tid = threadIdx.x;

    if (blockIdx.x < N_TRANS_BLK) {
        int i = blockIdx.x * 256 + tid;   // i < 589824 always
        int k = i % 9;
        int c = (i / 9) % C1_;
        int o = i / (9 * C1_);
        g_wt[(c * 9 + k) * C2_ + o] = w_dcn[i];
        if (blockIdx.x == 0) {   // zero the 4 pad rows (1024 floats)
            for (int z = tid; z < 4 * C2_; z += 256)
                g_wt[NROWS * C2_ + z] = 0.f;
        }
        return;
    }

    const int bx    = blockIdx.x - N_TRANS_BLK;
    const int strip = bx >> 2;
    const int slice = bx & 3;
    const int b     = strip >> 7;
    const int h     = (strip & 127) >> 1;
    const int w0    = (strip & 1) * 32;
    const int oc    = tid & 31;
    const int pg    = tid >> 5;

    float acc[4] = {0.f, 0.f, 0.f, 0.f};

    for (int c0 = slice * 64; c0 < slice * 64 + 64; c0 += 16) {
        __syncthreads();
        // input tile 16x3x34 (zero-padded)
        for (int t = tid; t < 16 * 3 * 34; t += 256) {
            int c   = t / 102;
            int rem = t - c * 102;
            int r   = rem / 34;
            int col = rem - r * 34;
            int gh = h + r - 1;
            int gw = w0 + col - 1;
            float v = 0.f;
            if (gh >= 0 && gh < H_ && gw >= 0 && gw < W_)
                v = in[((b * C2_ + c0 + c) * H_ + gh) * W_ + gw];
            sh[c][r][col] = v;
        }
        // weight tile 16x27x9
        for (int t = tid; t < 16 * 27 * 9; t += 256) {
            int c   = t / 243;
            int rem = t - c * 243;
            int o   = rem / 9;
            int k   = rem - o * 9;
            wsh[c][o][k] = w[((size_t)o * C2_ + c0 + c) * 9 + k];
        }
        __syncthreads();

        if (oc < OMC) {
            #pragma unroll 4
            for (int c = 0; c < 16; ++c) {
                #pragma unroll
                for (int ky = 0; ky < 3; ++ky) {
                    float r6[6];
                    #pragma unroll
                    for (int j = 0; j < 6; ++j) r6[j] = sh[c][ky][pg * 4 + j];
                    #pragma unroll
                    for (int kx = 0; kx < 3; ++kx) {
                        float wv = wsh[c][oc][ky * 3 + kx];
                        #pragma unroll
                        for (int p = 0; p < 4; ++p)
                            acc[p] += wv * r6[p + kx];
                    }
                }
            }
        }
    }

    if (oc < OMC) {
        float bo = (slice == 0) ? bias[oc] : 0.f;
        float* op = g_om[slice] + ((size_t)b * OMC + oc) * HW_ + h * W_ + w0 + pg * 4;
        #pragma unroll
        for (int p = 0; p < 4; ++p) op[p] = acc[p] + bo;
    }
}

// ---------------------------------------------------------------------------
// Kernel 2: deformable sampling + split-K GEMM + last-block reduction.
// Grid 1024: strip (b,h,32px) x 64-channel slice.
// GEMM: R8 memory pattern (4x LDG.32 weights, depth-4 ring, o0=tid&63,
// pg=tid>>6) + f32x2 FFMA2 body (BCAST2 weight duplication in registers).
// ---------------------------------------------------------------------------
__global__ __launch_bounds__(256, 3) void dcn_kernel(
    const float* __restrict__ x, const float* __restrict__ bias,
    float* __restrict__ out)
{
    __shared__ __align__(16) float val_sh[288][32];    // [c*9+k][px]  36 KB
    __shared__ int4   s_idx[288];                      // 4.5 KB
    __shared__ float4 s_w[288];                        // 4.5 KB
    __shared__ int    s_last;

    const int bx    = blockIdx.x;
    const int strip = bx >> 2;
    const int half  = bx & 3;
    const int cbase = half * 64;
    const int b     = strip >> 7;
    const int h     = (strip & 127) >> 1;
    const int w0    = (strip & 1) * 32;
    const int tid   = threadIdx.x;

    // ---- Phase 1: sampling metadata (per pixel x 9 taps) ----
    for (int e = tid; e < 288; e += 256) {
        int p  = e & 31;
        int k  = e >> 5;
        int ky = k / 3;
        int kx = k - ky * 3;
        int wo = w0 + p;
        const size_t base = (size_t)b * OMC * HW_ + h * W_ + wo;
        float dy = 0.f, dx = 0.f, mv = 0.f;
        #pragma unroll
        for (int s = 0; s < NSPLIT; ++s) {
            const float* omb = g_om[s] + base;
            dy += omb[(2 * k) * HW_];
            dx += omb[(2 * k + 1) * HW_];
            mv += omb[(18 + k) * HW_];
        }
        float m  = 1.f / (1.f + expf(-mv));

        float ys = (float)(h - 1 + ky) + dy;
        float xs = (float)(wo - 1 + kx) + dx;
        float y0f = floorf(ys), x0f = floorf(xs);
        float ly = ys - y0f, lx = xs - x0f;
        int y0 = (int)y0f, x0 = (int)x0f;
        int y1 = y0 + 1,   x1 = x0 + 1;

        bool vy0 = (y0 >= 0) && (y0 < H_);
        bool vy1 = (y1 >= 0) && (y1 < H_);
        bool vx0 = (x0 >= 0) && (x0 < W_);
        bool vx1 = (x1 >= 0) && (x1 < W_);
        int cy0 = min(max(y0, 0), H_ - 1), cy1 = min(max(y1, 0), H_ - 1);
        int cx0 = min(max(x0, 0), W_ - 1), cx1 = min(max(x1, 0), W_ - 1);

        float w00 = (vy0 && vx0) ? (1.f - ly) * (1.f - lx) * m : 0.f;
        float w01 = (vy0 && vx1) ? (1.f - ly) * lx * m : 0.f;
        float w10 = (vy1 && vx0) ? ly * (1.f - lx) * m : 0.f;
        float w11 = (vy1 && vx1) ? ly * lx * m : 0.f;

        s_idx[e] = make_int4(cy0 * W_ + cx0, cy0 * W_ + cx1,
                             cy1 * W_ + cx0, cy1 * W_ + cx1);
        s_w[e]   = make_float4(w00, w01, w10, w11);
    }
    __syncthreads();

    const int o0 = tid & 63;   // out-channel base (o0, +64, +128, +192)
    const int pg = tid >> 6;   // pixel-pair group (pixels pg*8..pg*8+7)
    const int gp = tid & 31;   // gather: pixel
    const int gc = tid >> 5;   // gather: channel sub-index (stride 8)

    unsigned long long acc2[4][4];
    #pragma unroll
    for (int j = 0; j < 4; ++j)
        #pragma unroll
        for (int pp = 0; pp < 4; ++pp) acc2[j][pp] = 0ULL;

    for (int c0 = cbase; c0 < cbase + 64; c0 += 32) {
        // ---- gather 32 channels x 9 taps x 32 pixels ----
        for (int cc = gc; cc < 32; cc += 8) {
            const float* xp = x + ((size_t)b * C1_ + c0 + cc) * HW_;
            #pragma unroll
            for (int k = 0; k < 9; ++k) {
                int e = k * 32 + gp;
                int4   id = s_idx[e];
                float4 wv = s_w[e];
                float v = wv.x * __ldg(xp + id.x) + wv.y * __ldg(xp + id.y)
                        + wv.z * __ldg(xp + id.z) + wv.w * __ldg(xp + id.w);
                val_sh[cc * 9 + k][gp] = v;
            }
        }
        __syncthreads();

        // ---- GEMM: 288 steps, 4x LDG.32 weights depth-4 ring, FFMA2 body ----
        const float* wtp = g_wt + (size_t)(c0 * 9) * C2_ + o0;
        float4 wreg[4];
        #pragma unroll
        for (int d = 0; d < 4; ++d) {
            const float* p = wtp + d * C2_;
            wreg[d] = make_float4(__ldg(p +   0), __ldg(p +  64),
                                  __ldg(p + 128), __ldg(p + 192));
        }

        for (int m = 0; m < 288; m += 4) {
            #pragma unroll
            for (int j = 0; j < 4; ++j) {
                const int ck = m + j;
                float4 wcur = wreg[j];
                // prefetch row ck+4 (pad rows keep this in-bounds at the tail)
                const float* wpn = wtp + (size_t)(ck + 4) * C2_;
                wreg[j] = make_float4(__ldg(wpn +   0), __ldg(wpn +  64),
                                      __ldg(wpn + 128), __ldg(wpn + 192));

                const ulonglong2* vp =
                    reinterpret_cast<const ulonglong2*>(&val_sh[ck][pg * 8]);
                ulonglong2 v01 = vp[0];
                ulonglong2 v23 = vp[1];

                unsigned long long wB0, wB1, wB2, wB3;
                BCAST2(wB0, wcur.x);
                BCAST2(wB1, wcur.y);
                BCAST2(wB2, wcur.z);
                BCAST2(wB3, wcur.w);

                FFMA2(acc2[0][0], wB0, v01.x);
                FFMA2(acc2[0][1], wB0, v01.y);
                FFMA2(acc2[0][2], wB0, v23.x);
                FFMA2(acc2[0][3], wB0, v23.y);
                FFMA2(acc2[1][0], wB1, v01.x);
                FFMA2(acc2[1][1], wB1, v01.y);
                FFMA2(acc2[1][2], wB1, v23.x);
                FFMA2(acc2[1][3], wB1, v23.y);
                FFMA2(acc2[2][0], wB2, v01.x);
                FFMA2(acc2[2][1], wB2, v01.y);
                FFMA2(acc2[2][2], wB2, v23.x);
                FFMA2(acc2[2][3], wB2, v23.y);
                FFMA2(acc2[3][0], wB3, v01.x);
                FFMA2(acc2[3][1], wB3, v01.y);
                FFMA2(acc2[3][2], wB3, v23.x);
                FFMA2(acc2[3][3], wB3, v23.y);
            }
        }
        __syncthreads();
    }

    // ---- write partials ----
    #pragma unroll
    for (int j = 0; j < 4; ++j) {
        int o = o0 + j * 64;
        float* op = g_part + (size_t)half * PART_SZ
                  + ((size_t)(b * C2_ + o)) * HW_ + h * W_ + w0 + pg * 8;
        #pragma unroll
        for (int pp = 0; pp < 4; ++pp) {
            float lo, hi;
            asm("mov.b64 {%0, %1}, %2;" : "=f"(lo), "=f"(hi) : "l"(acc2[j][pp]));
            op[pp * 2]     = lo;
            op[pp * 2 + 1] = hi;
        }
    }

    // ---- last-block reduction for this strip ----
    __threadfence();
    __syncthreads();
    if (tid == 0) {
        int old = atomicAdd(&g_cnt[strip], 1);
        s_last = (old == NSPLIT - 1);
        if (old == NSPLIT - 1) g_cnt[strip] = 0;   // reset for next graph replay
    }
    __syncthreads();

    if (s_last) {
        __threadfence();                 // acquire: see other blocks' partials
        const int oc = tid;              // 256 threads = 256 out channels
        const float bo = bias[oc];
        const size_t off = ((size_t)(b * C2_ + oc)) * HW_ + h * W_ + w0;
        #pragma unroll
        for (int px = 0; px < 32; px += 4) {
            float4 s = make_float4(bo, bo, bo, bo);
            #pragma unroll
            for (int sl = 0; sl < NSPLIT; ++sl) {
                float4 v = *reinterpret_cast<const float4*>(
                    g_part + (size_t)sl * PART_SZ + off + px);
                s.x += v.x; s.y += v.y; s.z += v.z; s.w += v.w;
            }
            *reinterpret_cast<float4*>(out + off + px) = s;
        }
    }
}

// ---------------------------------------------------------------------------
extern "C" void kernel_launch(void* const* d_in, const int* in_sizes, int n_in,
                              void* d_out, int out_size) {
    const float* x      = (const float*)d_in[0];
    const float* offs   = (const float*)d_in[1];
    const float* w_om   = (const float*)d_in[2];
    const float* b_om   = (const float*)d_in[3];
    const float* w_dcn  = (const float*)d_in[4];
    const float* b_dcn  = (const float*)d_in[5];
    float* out = (float*)d_out;

    prep_kernel<<<N_TRANS_BLK + N_CONV_BLK, 256>>>(offs, w_om, b_om, w_dcn);
    dcn_kernel<<<B_ * H_ * (W_ / 32) * NSPLIT, 256>>>(x, b_dcn, out);
}

// round 15
// speedup vs baseline: 1.4300x; 1.0431x over previous
#include <cuda_runtime.h>
#include <math.h>

#define B_   2
#define C1_  256
#define C2_  256
#define H_   64
#define W_   64
#define HW_  4096
#define OMC  27   // offset(18) + mask(9) channels

#define NSPLIT 4            // split-K factor (dcn)
#define OMSPLIT 8           // split-K factor (offset conv)
#define PART_SZ (B_ * C2_ * HW_)
#define OM_SZ   (B_ * OMC * HW_)

#define NROWS   (C1_ * 9)        // 2304 (c,k) rows
#define NROWS_P (NROWS + 4)      // + prefetch-overrun pad rows (zeros)

// Scratch (device globals — no allocation allowed)
__device__ float g_om[OMSPLIT][OM_SZ];             // offset/mask conv partials
__device__ float g_wt[NROWS_P * C2_];              // w_dcn transposed: [c][k][o]
__device__ float g_part[NSPLIT * PART_SZ];         // split-K partials (32 MB)
__device__ int   g_cnt[B_ * H_ * (W_ / 32)];       // per-strip counters (zero-init)

#define N_TRANS_BLK 2304   // transpose blocks (589824 elems / 256)
#define N_CONV_BLK  2048   // conv blocks (256 strips x 8 channel slices)

// f32x2 packed-FMA helpers (sm_100+ PTX; FFMA2 in SASS)
#define BCAST2(dst, s) asm("mov.b64 %0, {%1, %1};" : "=l"(dst) : "f"(s))
#define FFMA2(acc, a, b) \
    asm("fma.rn.f32x2 %0, %1, %2, %0;" : "+l"(acc) : "l"(a), "l"(b))

// ---------------------------------------------------------------------------
// Kernel 1 (merged): blocks [0,2304): transpose w_dcn [o][c][k] -> [c][k][o]
//                    blocks [2304,4352): 3x3 conv offset_feat -> g_om partials
//                    (256 strips x 8 slices of 32 channels; slice 0 adds bias)
// ---------------------------------------------------------------------------
__global__ __launch_bounds__(256) void prep_kernel(
    const float* __restrict__ in, const float* __restrict__ w,
    const float* __restrict__ bias, const float* __restrict__ w_dcn)
{
    __shared__ float sh[16][3][36];    // input tile: 16 ch x 3 rows x 34(+2) cols
    __shared__ float wsh[16][27][9];   // weight tile: 16 ch x 27 oc x 9 taps

    const int tid = threadIdx.x;

    if (blockIdx.x < N_TRANS_BLK) {
        int i = blockIdx.x * 256 + tid;   // i < 589824 always
        int k = i % 9;
        int c = (i / 9) % C1_;
        int o = i / (9 * C1_);
        g_wt[(c * 9 + k) * C2_ + o] = w_dcn[i];
        if (blockIdx.x == 0) {   // zero the 4 pad rows (1024 floats)
            for (int z = tid; z < 4 * C2_; z += 256)
                g_wt[NROWS * C2_ + z] = 0.f;
        }
        return;
    }

    const int bx    = blockIdx.x - N_TRANS_BLK;
    const int strip = bx >> 3;
    const int slice = bx & 7;
    const int b     = strip >> 7;
    const int h     = (strip & 127) >> 1;
    const int w0    = (strip & 1) * 32;
    const int oc    = tid & 31;
    const int pg    = tid >> 5;

    float acc[4] = {0.f, 0.f, 0.f, 0.f};

    for (int c0 = slice * 32; c0 < slice * 32 + 32; c0 += 16) {
        __syncthreads();
        // input tile 16x3x34 (zero-padded)
        for (int t = tid; t < 16 * 3 * 34; t += 256) {
            int c   = t / 102;
            int rem = t - c * 102;
            int r   = rem / 34;
            int col = rem - r * 34;
            int gh = h + r - 1;
            int gw = w0 + col - 1;
            float v = 0.f;
            if (gh >= 0 && gh < H_ && gw >= 0 && gw < W_)
                v = in[((b * C2_ + c0 + c) * H_ + gh) * W_ + gw];
            sh[c][r][col] = v;
        }
        // weight tile 16x27x9
        for (int t = tid; t < 16 * 27 * 9; t += 256) {
            int c   = t / 243;
            int rem = t - c * 243;
            int o   = rem / 9;
            int k   = rem - o * 9;
            wsh[c][o][k] = w[((size_t)o * C2_ + c0 + c) * 9 + k];
        }
        __syncthreads();

        if (oc < OMC) {
            #pragma unroll 4
            for (int c = 0; c < 16; ++c) {
                #pragma unroll
                for (int ky = 0; ky < 3; ++ky) {
                    float r6[6];
                    #pragma unroll
                    for (int j = 0; j < 6; ++j) r6[j] = sh[c][ky][pg * 4 + j];
                    #pragma unroll
                    for (int kx = 0; kx < 3; ++kx) {
                        float wv = wsh[c][oc][ky * 3 + kx];
                        #pragma unroll
                        for (int p = 0; p < 4; ++p)
                            acc[p] += wv * r6[p + kx];
                    }
                }
            }
        }
    }

    if (oc < OMC) {
        float bo = (slice == 0) ? bias[oc] : 0.f;
        float* op = g_om[slice] + ((size_t)b * OMC + oc) * HW_ + h * W_ + w0 + pg * 4;
        #pragma unroll
        for (int p = 0; p < 4; ++p) op[p] = acc[p] + bo;
    }
}

// ---------------------------------------------------------------------------
// Kernel 2: deformable sampling + split-K GEMM + last-block reduction.
// Grid 1024: strip (b,h,32px) x 64-channel slice.
// Gather: k outer (meta in regs), cc inner (16 LDGs in flight).
// GEMM: 4x LDG.32 weights depth-4 ring + f32x2 FFMA2 body (R14 — proven).
// ---------------------------------------------------------------------------
__global__ __launch_bounds__(256, 3) void dcn_kernel(
    const float* __restrict__ x, const float* __restrict__ bias,
    float* __restrict__ out)
{
    __shared__ __align__(16) float val_sh[288][32];    // [c*9+k][px]  36 KB
    __shared__ int4   s_idx[288];                      // 4.5 KB
    __shared__ float4 s_w[288];                        // 4.5 KB
    __shared__ int    s_last;

    const int bx    = blockIdx.x;
    const int strip = bx >> 2;
    const int half  = bx & 3;
    const int cbase = half * 64;
    const int b     = strip >> 7;
    const int h     = (strip & 127) >> 1;
    const int w0    = (strip & 1) * 32;
    const int tid   = threadIdx.x;

    // ---- Phase 1: sampling metadata (per pixel x 9 taps) ----
    for (int e = tid; e < 288; e += 256) {
        int p  = e & 31;
        int k  = e >> 5;
        int ky = k / 3;
        int kx = k - ky * 3;
        int wo = w0 + p;
        const size_t base = (size_t)b * OMC * HW_ + h * W_ + wo;
        float dy = 0.f, dx = 0.f, mv = 0.f;
        #pragma unroll
        for (int s = 0; s < OMSPLIT; ++s) {
            const float* omb = g_om[s] + base;
            dy += omb[(2 * k) * HW_];
            dx += omb[(2 * k + 1) * HW_];
            mv += omb[(18 + k) * HW_];
        }
        float m  = 1.f / (1.f + expf(-mv));

        float ys = (float)(h - 1 + ky) + dy;
        float xs = (float)(wo - 1 + kx) + dx;
        float y0f = floorf(ys), x0f = floorf(xs);
        float ly = ys - y0f, lx = xs - x0f;
        int y0 = (int)y0f, x0 = (int)x0f;
        int y1 = y0 + 1,   x1 = x0 + 1;

        bool vy0 = (y0 >= 0) && (y0 < H_);
        bool vy1 = (y1 >= 0) && (y1 < H_);
        bool vx0 = (x0 >= 0) && (x0 < W_);
        bool vx1 = (x1 >= 0) && (x1 < W_);
        int cy0 = min(max(y0, 0), H_ - 1), cy1 = min(max(y1, 0), H_ - 1);
        int cx0 = min(max(x0, 0), W_ - 1), cx1 = min(max(x1, 0), W_ - 1);

        float w00 = (vy0 && vx0) ? (1.f - ly) * (1.f - lx) * m : 0.f;
        float w01 = (vy0 && vx1) ? (1.f - ly) * lx * m : 0.f;
        float w10 = (vy1 && vx0) ? ly * (1.f - lx) * m : 0.f;
        float w11 = (vy1 && vx1) ? ly * lx * m : 0.f;

        s_idx[e] = make_int4(cy0 * W_ + cx0, cy0 * W_ + cx1,
                             cy1 * W_ + cx0, cy1 * W_ + cx1);
        s_w[e]   = make_float4(w00, w01, w10, w11);
    }
    __syncthreads();

    const int o0 = tid & 63;   // out-channel base (o0, +64, +128, +192)
    const int pg = tid >> 6;   // pixel-pair group (pixels pg*8..pg*8+7)
    const int gp = tid & 31;   // gather: pixel
    const int gc = tid >> 5;   // gather: channel sub-index (stride 8)

    unsigned long long acc2[4][4];
    #pragma unroll
    for (int j = 0; j < 4; ++j)
        #pragma unroll
        for (int pp = 0; pp < 4; ++pp) acc2[j][pp] = 0ULL;

    for (int c0 = cbase; c0 < cbase + 64; c0 += 32) {
        // ---- gather 32 ch x 9 taps x 32 px: k outer (meta in regs) ----
        const float* xbase = x + ((size_t)b * C1_ + c0 + gc) * HW_;
        #pragma unroll
        for (int k = 0; k < 9; ++k) {
            int e = k * 32 + gp;
            int4   id = s_idx[e];
            float4 wv = s_w[e];
            #pragma unroll
            for (int cc = 0; cc < 4; ++cc) {
                const float* xp = xbase + (size_t)(cc * 8) * HW_;
                float v = wv.x * __ldg(xp + id.x) + wv.y * __ldg(xp + id.y)
                        + wv.z * __ldg(xp + id.z) + wv.w * __ldg(xp + id.w);
                val_sh[(gc + cc * 8) * 9 + k][gp] = v;
            }
        }
        __syncthreads();

        // ---- GEMM: 288 steps, 4x LDG.32 weights depth-4 ring, FFMA2 body ----
        const float* wtp = g_wt + (size_t)(c0 * 9) * C2_ + o0;
        float4 wreg[4];
        #pragma unroll
        for (int d = 0; d < 4; ++d) {
            const float* p = wtp + d * C2_;
            wreg[d] = make_float4(__ldg(p +   0), __ldg(p +  64),
                                  __ldg(p + 128), __ldg(p + 192));
        }

        for (int m = 0; m < 288; m += 4) {
            #pragma unroll
            for (int j = 0; j < 4; ++j) {
                const int ck = m + j;
                float4 wcur = wreg[j];
                // prefetch row ck+4 (pad rows keep this in-bounds at the tail)
                const float* wpn = wtp + (size_t)(ck + 4) * C2_;
                wreg[j] = make_float4(__ldg(wpn +   0), __ldg(wpn +  64),
                                      __ldg(wpn + 128), __ldg(wpn + 192));

                const ulonglong2* vp =
                    reinterpret_cast<const ulonglong2*>(&val_sh[ck][pg * 8]);
                ulonglong2 v01 = vp[0];
                ulonglong2 v23 = vp[1];

                unsigned long long wB0, wB1, wB2, wB3;
                BCAST2(wB0, wcur.x);
                BCAST2(wB1, wcur.y);
                BCAST2(wB2, wcur.z);
                BCAST2(wB3, wcur.w);

                FFMA2(acc2[0][0], wB0, v01.x);
                FFMA2(acc2[0][1], wB0, v01.y);
                FFMA2(acc2[0][2], wB0, v23.x);
                FFMA2(acc2[0][3], wB0, v23.y);
                FFMA2(acc2[1][0], wB1, v01.x);
                FFMA2(acc2[1][1], wB1, v01.y);
                FFMA2(acc2[1][2], wB1, v23.x);
                FFMA2(acc2[1][3], wB1, v23.y);
                FFMA2(acc2[2][0], wB2, v01.x);
                FFMA2(acc2[2][1], wB2, v01.y);
                FFMA2(acc2[2][2], wB2, v23.x);
                FFMA2(acc2[2][3], wB2, v23.y);
                FFMA2(acc2[3][0], wB3, v01.x);
                FFMA2(acc2[3][1], wB3, v01.y);
                FFMA2(acc2[3][2], wB3, v23.x);
                FFMA2(acc2[3][3], wB3, v23.y);
            }
        }
        __syncthreads();
    }

    // ---- write partials ----
    #pragma unroll
    for (int j = 0; j < 4; ++j) {
        int o = o0 + j * 64;
        float* op = g_part + (size_t)half * PART_SZ
                  + ((size_t)(b * C2_ + o)) * HW_ + h * W_ + w0 + pg * 8;
        #pragma unroll
        for (int pp = 0; pp < 4; ++pp) {
            float lo, hi;
            asm("mov.b64 {%0, %1}, %2;" : "=f"(lo), "=f"(hi) : "l"(acc2[j][pp]));
            op[pp * 2]     = lo;
            op[pp * 2 + 1] = hi;
        }
    }

    // ---- last-block reduction for this strip ----
    __threadfence();
    __syncthreads();
    if (tid == 0) {
        int old = atomicAdd(&g_cnt[strip], 1);
        s_last = (old == NSPLIT - 1);
        if (old == NSPLIT - 1) g_cnt[strip] = 0;   // reset for next graph replay
    }
    __syncthreads();

    if (s_last) {
        __threadfence();                 // acquire: see other blocks' partials
        const int oc = tid;              // 256 threads = 256 out channels
        const float bo = bias[oc];
        const size_t off = ((size_t)(b * C2_ + oc)) * HW_ + h * W_ + w0;
        #pragma unroll
        for (int px = 0; px < 32; px += 4) {
            float4 s = make_float4(bo, bo, bo, bo);
            #pragma unroll
            for (int sl = 0; sl < NSPLIT; ++sl) {
                float4 v = *reinterpret_cast<const float4*>(
                    g_part + (size_t)sl * PART_SZ + off + px);
                s.x += v.x; s.y += v.y; s.z += v.z; s.w += v.w;
            }
            *reinterpret_cast<float4*>(out + off + px) = s;
        }
    }
}

// ---------------------------------------------------------------------------
extern "C" void kernel_launch(void* const* d_in, const int* in_sizes, int n_in,
                              void* d_out, int out_size) {
    const float* x      = (const float*)d_in[0];
    const float* offs   = (const float*)d_in[1];
    const float* w_om   = (const float*)d_in[2];
    const float* b_om   = (const float*)d_in[3];
    const float* w_dcn  = (const float*)d_in[4];
    const float* b_dcn  = (const float*)d_in[5];
    float* out = (float*)d_out;

    prep_kernel<<<N_TRANS_BLK + N_CONV_BLK, 256>>>(offs, w_om, b_om, w_dcn);
    dcn_kernel<<<B_ * H_ * (W_ / 32) * NSPLIT, 256>>>(x, b_dcn, out);
}